// round 13
// baseline (speedup 1.0000x reference)
#include <cuda_runtime.h>
#include <math.h>
#include <stdint.h>

#define NN   20000
#define EE   160000
#define CC   64
#define SHD  9
#define SD   16
#define KM   2000
#define EV   32000
#define E2   (EE + EV)          /* 192000 */
#define CSH  576
#define ECH  32000              /* edges per U chunk (73.7 MB, L2-resident) */
#define FLIP_ZERO 0x80000000u
#define NBT  ((KM*KM + 1023)/1024)   /* 3907 tie-chunks */

#define OUT_H   0
#define OUT_POS 1280000
#define OUT_A   1340000
#define OUT_M   5340000

/* ----------------------------- scratch ----------------------------------- */
static __device__ float g_sh   [(size_t)E2 * SHD];
static __device__ float g_hid  [(size_t)E2 * CC];
static __device__ float g_U    [(size_t)ECH * CSH];   /* chunk-local */
static __device__ float g_agg  [NN * CC];
static __device__ float g_deg  [NN];
static __device__ float g_hloc [NN * CC];
static __device__ float g_score[NN];
static __device__ float g_m    [NN];
static __device__ int   g_master[KM];
static __device__ int   g_node2m[NN];
static __device__ float g_hm   [KM * CC];
static __device__ float g_posm [KM * 3];
static __device__ float g_q    [KM * SD];
static __device__ float g_kk   [KM * SD];
static __device__ float g_adj  [(size_t)KM * KM];
static __device__ float g_cand [(size_t)KM * KM];
static __device__ int   g_src2 [E2];
static __device__ int   g_dst2 [E2];
static __device__ float g_mask2[E2];
static __device__ float g_agg2 [KM * CC];
static __device__ float g_deg2 [KM];
static __device__ float g_hhier[KM * CC];
static __device__ unsigned g_hist[256];
static __device__ unsigned g_tiecnt[NBT];
static __device__ unsigned g_tieoff[NBT];
/* [0]=prefix [1]=T [2]=needTie [3]=need [4]=cntGt [5]=P [6]=emitCtr [7]=totalSel */
static __device__ unsigned g_state[8];

/* ----------------------------- helpers ----------------------------------- */
__device__ __forceinline__ unsigned fl(float x) {
    unsigned u = __float_as_uint(x);
    return (u & 0x80000000u) ? ~u : (u | 0x80000000u);
}
__device__ __forceinline__ float sigm(float x) {
    return (x >= 0.f) ? 1.f / (1.f + expf(-x)) : expf(x) / (1.f + expf(x));
}
/* packed f32x2 helpers (FFMA2 — halves fma-pipe instr; halves are exact FMAs) */
__device__ __forceinline__ unsigned long long pk2(float a) {
    unsigned long long r;
    asm("mov.b64 %0, {%1, %1};" : "=l"(r) : "r"(__float_as_uint(a)));
    return r;
}
__device__ __forceinline__ void fma2(unsigned long long& acc,
                                     unsigned long long a, unsigned long long b) {
    asm("fma.rn.f32x2 %0, %1, %2, %0;" : "+l"(acc) : "l"(a), "l"(b));
}
__device__ __forceinline__ void upk2(unsigned long long v, float& lo, float& hi) {
    unsigned l, h;
    asm("mov.b64 {%0, %1}, %2;" : "=r"(l), "=r"(h) : "l"(v));
    lo = __uint_as_float(l); hi = __uint_as_float(h);
}
__device__ __forceinline__ unsigned blockScanIncl(unsigned v, unsigned* ws) {
    unsigned x = v;
    #pragma unroll
    for (int o = 1; o < 32; o <<= 1) {
        unsigned t = __shfl_up_sync(0xFFFFFFFFu, x, o);
        if ((threadIdx.x & 31) >= o) x += t;
    }
    if ((threadIdx.x & 31) == 31) ws[threadIdx.x >> 5] = x;
    __syncthreads();
    if (threadIdx.x < 32) {
        unsigned w = ws[threadIdx.x];
        #pragma unroll
        for (int o = 1; o < 32; o <<= 1) {
            unsigned t = __shfl_up_sync(0xFFFFFFFFu, w, o);
            if ((int)threadIdx.x >= o) w += t;
        }
        ws[threadIdx.x] = w;
    }
    __syncthreads();
    if (threadIdx.x >= 32) x += ws[(threadIdx.x >> 5) - 1];
    return x;
}

/* ------------------------------ clear ------------------------------------ */
__global__ void k_clear() {
    int i  = blockIdx.x * blockDim.x + threadIdx.x;
    int st = gridDim.x * blockDim.x;
    for (int t = i; t < KM * KM; t += st) g_adj[t] = 0.f;
    for (int t = i; t < NN * CC; t += st) g_agg[t] = 0.f;
    for (int t = i; t < NN;      t += st) g_deg[t] = 0.f;
    for (int t = i; t < KM * CC; t += st) g_agg2[t] = 0.f;
    for (int t = i; t < KM;      t += st) g_deg2[t] = 0.f;
    if (i < 256) g_hist[i] = 0;
    if (i < 8)   g_state[i] = (i == 3) ? (unsigned)EV : 0u;
}

/* -------------------- geometry: sh + bessel->hidden ---------------------- */
__global__ __launch_bounds__(256)
void k_geom(int c2, const int* __restrict__ src, const int* __restrict__ dst,
            const float* __restrict__ pos,
            const float* __restrict__ fw1, const float* __restrict__ fb1, int n)
{
    __shared__ float sw1[8 * CC];
    __shared__ float sb1[CC];
    if (c2) { src = g_src2; dst = g_dst2; pos = g_posm; }
    int tid = threadIdx.x;
    for (int t = tid; t < 8 * CC; t += 256) sw1[t] = fw1[t];
    if (tid < CC) sb1[tid] = fb1[tid];
    __syncthreads();
    int e = blockIdx.x * 256 + tid;
    if (e >= n) return;
    if (c2 && g_mask2[e] == 0.f) return;
    int si = src[e], di = dst[e];
    float vx = pos[si*3+0] - pos[di*3+0];
    float vy = pos[si*3+1] - pos[di*3+1];
    float vz = pos[si*3+2] - pos[di*3+2];
    float r  = sqrtf(vx*vx + vy*vy + vz*vz + 1e-12f);
    float iv = 1.0f / r;
    float x = vx*iv, y = vy*iv, z = vz*iv;
    const float s3  = 1.7320508075688772f;
    const float s15 = 3.8729833462074170f;
    const float s5  = 2.2360679774997896f;
    float* so = g_sh + (size_t)e * SHD;
    so[0] = 1.0f;
    so[1] = s3 * x;  so[2] = s3 * y;  so[3] = s3 * z;
    so[4] = s15 * x * y;  so[5] = s15 * y * z;
    so[6] = 0.5f * s5 * (3.0f * z * z - 1.0f);
    so[7] = s15 * x * z;
    so[8] = 0.5f * s15 * (x * x - y * y);
    float rc = fmaxf(r, 1e-9f);
    float u  = fminf(r * 0.2f, 1.0f);
    float u2 = u*u, u4 = u2*u2, u6 = u4*u2;
    float env  = 1.0f - 28.0f*u6 + 48.0f*u6*u - 21.0f*u6*u2;
    float pref = 0.6324555320336759f / rc * env;
    float w0r  = 0.6283185307179586f * r;
    float ef[8];
    #pragma unroll
    for (int nb = 0; nb < 8; nb++) ef[nb] = pref * sinf((float)(nb+1) * w0r);
    float* ho = g_hid + (size_t)e * CC;
    #pragma unroll 4
    for (int o4 = 0; o4 < CC; o4 += 4) {
        float a0 = sb1[o4+0], a1 = sb1[o4+1], a2 = sb1[o4+2], a3 = sb1[o4+3];
        #pragma unroll
        for (int nb = 0; nb < 8; nb++) {
            float efn = ef[nb];
            a0 = fmaf(efn, sw1[nb*CC + o4+0], a0);
            a1 = fmaf(efn, sw1[nb*CC + o4+1], a1);
            a2 = fmaf(efn, sw1[nb*CC + o4+2], a2);
            a3 = fmaf(efn, sw1[nb*CC + o4+3], a3);
        }
        float4 v;
        v.x = fmaxf(a0, 0.f); v.y = fmaxf(a1, 0.f);
        v.z = fmaxf(a2, 0.f); v.w = fmaxf(a3, 0.f);
        *(float4*)(ho + o4) = v;
    }
}

/* ------- GEMM1: U[e,cs] = (hid@fc_w2 + b2) * h[dst,cs/9] * sh[e,cs%9] ----
   chunked: g_U holds edges [eChunk, eChunk+ECH); swizzled A-tile + FFMA2. */
__global__ __launch_bounds__(256)
void k_gemm1(int c2, const float* __restrict__ hf, const int* __restrict__ dst,
             const float* __restrict__ w2, const float* __restrict__ b2,
             int eChunk)
{
    __shared__ float As[64 * 64];
    __shared__ float Bs[64][68];
    if (c2) { hf = g_hm; dst = g_dst2; }
    int eBase = eChunk + blockIdx.x * 64, nBase = blockIdx.y * 64;
    int tid = threadIdx.x;
    if (c2) {
        int p = (tid < 64) ? (g_mask2[eBase + tid] != 0.f) : 0;
        if (__syncthreads_count(p) == 0) return;
    }
    int lr = tid >> 4, t4 = tid & 15, lc4 = t4 * 4;
    #pragma unroll
    for (int rep = 0; rep < 4; rep++) {
        int row = lr + rep * 16;
        float4 a = *(const float4*)(g_hid + (size_t)(eBase + row) * CC + lc4);
        int sw = (((row >> 2) ^ t4) << 2) + (row & 3);
        As[(lc4+0)*64 + sw] = a.x;
        As[(lc4+1)*64 + sw] = a.y;
        As[(lc4+2)*64 + sw] = a.z;
        As[(lc4+3)*64 + sw] = a.w;
        float4 b = *(const float4*)(w2 + (size_t)row * CSH + nBase + lc4);
        *(float4*)&Bs[row][lc4] = b;
    }
    __syncthreads();
    int ty = tid >> 4, tx = tid & 15;
    unsigned long long acc[4][2] = {};
    #pragma unroll 8
    for (int k = 0; k < 64; k++) {
        float4 a4 = *(const float4*)&As[k*64 + ((ty ^ (k >> 2)) << 2)];
        ulonglong2 bv = *(const ulonglong2*)&Bs[k][tx*4];
        unsigned long long a0 = pk2(a4.x), a1 = pk2(a4.y);
        unsigned long long a2 = pk2(a4.z), a3 = pk2(a4.w);
        fma2(acc[0][0], a0, bv.x); fma2(acc[0][1], a0, bv.y);
        fma2(acc[1][0], a1, bv.x); fma2(acc[1][1], a1, bv.y);
        fma2(acc[2][0], a2, bv.x); fma2(acc[2][1], a2, bv.y);
        fma2(acc[3][0], a3, bv.x); fma2(acc[3][1], a3, bv.y);
    }
    #pragma unroll
    for (int i = 0; i < 4; i++) {
        int e = eBase + ty*4 + i;
        int d = dst[e];
        const float* he = hf + (size_t)d * CC;
        const float* se = g_sh + (size_t)e * SHD;
        int cs0 = nBase + tx*4;
        float av[4];
        upk2(acc[i][0], av[0], av[1]);
        upk2(acc[i][1], av[2], av[3]);
        float4 o;
        {
            int cs = cs0+0; int c = cs/9, s = cs - c*9;
            o.x = (av[0] + b2[cs]) * he[c] * se[s];
        }{
            int cs = cs0+1; int c = cs/9, s = cs - c*9;
            o.y = (av[1] + b2[cs]) * he[c] * se[s];
        }{
            int cs = cs0+2; int c = cs/9, s = cs - c*9;
            o.z = (av[2] + b2[cs]) * he[c] * se[s];
        }{
            int cs = cs0+3; int c = cs/9, s = cs - c*9;
            o.w = (av[3] + b2[cs]) * he[c] * se[s];
        }
        *(float4*)(g_U + (size_t)(e - eChunk) * CSH + cs0) = o;
    }
}

/* ----------- GEMM2: msg = U @ lin_w ; atomic scatter by src -------------- */
__global__ __launch_bounds__(256)
void k_gemm2(int c2, const int* __restrict__ src, const float* __restrict__ lw,
             int eChunk)
{
    __shared__ float As[64 * 64];
    __shared__ float Bs[64][68];
    const float* msk = 0;
    float* agg = g_agg;
    if (c2) { src = g_src2; msk = g_mask2; agg = g_agg2; }
    int eBase = eChunk + blockIdx.x * 64;
    int tid = threadIdx.x;
    if (c2) {
        int p = (tid < 64) ? (g_mask2[eBase + tid] != 0.f) : 0;
        if (__syncthreads_count(p) == 0) return;
    }
    int lr = tid >> 4, t4 = tid & 15, lc4 = t4 * 4;
    int ty = tid >> 4, tx = tid & 15;
    int uBase = eBase - eChunk;
    unsigned long long acc[4][2] = {};
    for (int kt = 0; kt < 9; kt++) {
        #pragma unroll
        for (int rep = 0; rep < 4; rep++) {
            int row = lr + rep * 16;
            float4 a = *(const float4*)(g_U + (size_t)(uBase + row) * CSH + kt*64 + lc4);
            int sw = (((row >> 2) ^ t4) << 2) + (row & 3);
            As[(lc4+0)*64 + sw] = a.x;
            As[(lc4+1)*64 + sw] = a.y;
            As[(lc4+2)*64 + sw] = a.z;
            As[(lc4+3)*64 + sw] = a.w;
            float4 b = *(const float4*)(lw + (size_t)(kt*64 + row) * CC + lc4);
            *(float4*)&Bs[row][lc4] = b;
        }
        __syncthreads();
        #pragma unroll 8
        for (int k = 0; k < 64; k++) {
            float4 a4 = *(const float4*)&As[k*64 + ((ty ^ (k >> 2)) << 2)];
            ulonglong2 bv = *(const ulonglong2*)&Bs[k][tx*4];
            unsigned long long a0 = pk2(a4.x), a1 = pk2(a4.y);
            unsigned long long a2 = pk2(a4.z), a3 = pk2(a4.w);
            fma2(acc[0][0], a0, bv.x); fma2(acc[0][1], a0, bv.y);
            fma2(acc[1][0], a1, bv.x); fma2(acc[1][1], a1, bv.y);
            fma2(acc[2][0], a2, bv.x); fma2(acc[2][1], a2, bv.y);
            fma2(acc[3][0], a3, bv.x); fma2(acc[3][1], a3, bv.y);
        }
        __syncthreads();
    }
    #pragma unroll
    for (int i = 0; i < 4; i++) {
        int e = eBase + ty*4 + i;
        float mm = msk ? msk[e] : 1.f;
        if (mm != 0.f) {
            int s = src[e];
            float av[4];
            upk2(acc[i][0], av[0], av[1]);
            upk2(acc[i][1], av[2], av[3]);
            float* ap = agg + (size_t)s * CC + tx*4;
            atomicAdd(ap+0, av[0]);
            atomicAdd(ap+1, av[1]);
            atomicAdd(ap+2, av[2]);
            atomicAdd(ap+3, av[3]);
        }
    }
}

__global__ void k_deg(int c2, const int* __restrict__ src, int n)
{
    const float* msk = 0; float* deg = g_deg;
    if (c2) { src = g_src2; msk = g_mask2; deg = g_deg2; }
    int e = blockIdx.x * blockDim.x + threadIdx.x;
    if (e >= n) return;
    float mm = msk ? msk[e] : 1.f;
    if (mm != 0.f) atomicAdd(&deg[src[e]], mm);
}

/* ------------------------- h_local + score MLP --------------------------- */
__global__ void k_update(const float* __restrict__ h)
{
    int t = blockIdx.x * blockDim.x + threadIdx.x;
    if (t >= NN * CC) return;
    int n = t >> 6;
    g_hloc[t] = g_agg[t] / fmaxf(g_deg[n], 1.f) + h[t];
}

__global__ __launch_bounds__(128)
void k_score(const float* __restrict__ w1, const float* __restrict__ b1,
             const float* __restrict__ w2, const float* __restrict__ b2)
{
    __shared__ float sw1[SD * 64];
    __shared__ float sb1[64];
    __shared__ float sw2[64];
    int tid = threadIdx.x;
    for (int t = tid; t < SD*64; t += 128) sw1[t] = w1[t];
    if (tid < 64) { sb1[tid] = b1[tid]; sw2[tid] = w2[tid]; }
    __syncthreads();
    int i = blockIdx.x * 128 + tid;
    if (i >= NN) return;
    float hs[SD];
    #pragma unroll
    for (int c = 0; c < SD; c++) hs[c] = g_hloc[(size_t)i * CC + c];
    float sum = 0.f;
    for (int j = 0; j < 64; j++) {
        float a = sb1[j];
        #pragma unroll
        for (int c = 0; c < SD; c++) a = fmaf(hs[c], sw1[c*64 + j], a);
        sum = fmaf(fmaxf(a, 0.f), sw2[j], sum);
    }
    g_score[i] = sigm(sum + b2[0]);
}

/* -------- exact top-K of scores (desc value, asc index tie-break) -------- */
__global__ __launch_bounds__(1024)
void k_topk()
{
    __shared__ unsigned hist[256];
    __shared__ unsigned ws[32];
    __shared__ unsigned sPre, sNeed;
    int tid = threadIdx.x;
    unsigned prefix = 0, need = KM;
    for (int round = 0; round < 4; round++) {
        int shift = 24 - 8*round;
        if (tid < 256) hist[tid] = 0;
        __syncthreads();
        for (int i = tid; i < NN; i += 1024) {
            unsigned f = fl(g_score[i]);
            if (round == 0 || (f >> (shift+8)) == (prefix >> (shift+8)))
                atomicAdd(&hist[(f >> shift) & 255], 1u);
        }
        __syncthreads();
        if (tid == 0) {
            unsigned cum = 0; int b = 255;
            for (; b > 0; b--) { unsigned c = hist[b]; if (cum + c >= need) break; cum += c; }
            sPre = prefix | ((unsigned)b << shift);
            sNeed = need - cum;
        }
        __syncthreads();
        prefix = sPre; need = sNeed;
        __syncthreads();
    }
    unsigned T = prefix, needTie = need;
    unsigned runSel = 0, runTie = 0;
    for (int base = 0; base < NN; base += 1024) {
        int i = base + tid;
        int valid = i < NN;
        float sc = valid ? g_score[i] : 0.f;
        unsigned f = valid ? fl(sc) : 0u;
        unsigned isGt  = (valid && f >  T) ? 1u : 0u;
        unsigned isTie = (valid && f == T) ? 1u : 0u;
        unsigned pk = isGt | (isTie << 16);
        unsigned incl = blockScanIncl(pk, ws);
        unsigned excl = incl - pk;
        unsigned gtE = excl & 0xFFFFu, tieE = excl >> 16;
        unsigned remTie = (needTie > runTie) ? needTie - runTie : 0u;
        int take = isGt || (isTie && tieE < remTie);
        unsigned rank = runSel + gtE + (tieE < remTie ? tieE : remTie);
        if (valid) {
            if (take) { g_master[rank] = i; g_node2m[i] = (int)rank; g_m[i] = sc; }
            else      { g_node2m[i] = -1;   g_m[i] = 0.f; }
        }
        unsigned tot = ws[31];
        unsigned totGt = tot & 0xFFFFu, totTie = tot >> 16;
        runSel += totGt + (totTie < remTie ? totTie : remTie);
        runTie += totTie;
        __syncthreads();
    }
}

/* ----------------------- master gather + q/k ----------------------------- */
__global__ void k_master(const float* __restrict__ pos)
{
    int t = blockIdx.x * blockDim.x + threadIdx.x;
    if (t < KM * CC) {
        int j = t >> 6, c = t & 63;
        g_hm[t] = g_hloc[(size_t)g_master[j] * CC + c];
    }
    if (t < KM * 3) {
        g_posm[t] = pos[(size_t)g_master[t/3] * 3 + (t - (t/3)*3)];
    }
}

__global__ void k_qk(const float* __restrict__ wq, const float* __restrict__ wk)
{
    int t = blockIdx.x * blockDim.x + threadIdx.x;
    if (t >= KM * 32) return;
    int j = t >> 5, u = t & 31;
    const float* hm = g_hm + (size_t)j * CC;
    if (u < 16) {
        float a = 0.f;
        #pragma unroll
        for (int i = 0; i < SD; i++) a = fmaf(hm[i], wq[i*SD + u], a);
        g_q[j*SD + u] = a;
    } else {
        int uu = u - 16;
        float a = 0.f;
        #pragma unroll
        for (int i = 0; i < SD; i++) a = fmaf(hm[i], wk[i*SD + uu], a);
        g_kk[j*SD + uu] = a;
    }
}

/* ----------------- adjacency scatter + master edge remap ----------------- */
__global__ void k_adjsc(const int* __restrict__ src, const int* __restrict__ dst)
{
    int e = blockIdx.x * blockDim.x + threadIdx.x;
    if (e >= EE) return;
    int sm = g_node2m[src[e]], dm = g_node2m[dst[e]];
    int ok = (sm >= 0) && (dm >= 0);
    g_src2[e] = sm >= 0 ? sm : 0;
    g_dst2[e] = dm >= 0 ? dm : 0;
    g_mask2[e] = ok ? 1.f : 0.f;
    if (ok) atomicAdd(&g_adj[(size_t)sm * KM + dm], 1.f);
}

/* ------------------- attention + A_virtual + candidates ------------------ */
__global__ __launch_bounds__(1024)
void k_attn(float* __restrict__ outA)
{
    __shared__ float qt[32][16];
    __shared__ float kt[32][17];
    int j0 = blockIdx.x * 32, i0 = blockIdx.y * 32;
    int tx = threadIdx.x, ty = threadIdx.y;
    int i = i0 + ty, j = j0 + tx;
    if (tx < 16) {
        qt[ty][tx] = (i < KM) ? g_q[(size_t)i*SD + tx] : 0.f;
        kt[ty][tx] = (j0 + ty < KM) ? g_kk[(size_t)(j0+ty)*SD + tx] : 0.f;
    }
    __syncthreads();
    int p = 0;
    if (i < KM && j < KM) {
        float d = 0.f;
        #pragma unroll
        for (int t = 0; t < SD; t++) d = fmaf(qt[ty][t], kt[tx][t], d);
        float at = sigm(d * 0.25f);
        bool exist = (g_adj[(size_t)i*KM + j] > 0.f) || (i == j);
        float av = (!exist && at > 0.5f) ? 1.f : 0.f;
        outA[(size_t)i*KM + j] = av;
        float cd = av * at;
        g_cand[(size_t)i*KM + j] = cd;
        p = cd > 0.f;
    }
    int cnt = __syncthreads_count(p);
    if (tx == 0 && ty == 0 && cnt) atomicAdd(&g_state[5], (unsigned)cnt);
}

/* ----------------- global radix select for top-E_V edges ----------------- */
__global__ __launch_bounds__(256)
void k_ghist(int shift, int first)
{
    __shared__ unsigned h[256];
    if (threadIdx.x < 256) h[threadIdx.x] = 0;
    __syncthreads();
    unsigned prefix = g_state[0];
    int n = KM * KM;
    for (int i = blockIdx.x * blockDim.x + threadIdx.x; i < n;
         i += gridDim.x * blockDim.x) {
        unsigned f = fl(g_cand[i]);
        if (first || (f >> (shift+8)) == (prefix >> (shift+8)))
            atomicAdd(&h[(f >> shift) & 255], 1u);
    }
    __syncthreads();
    if (threadIdx.x < 256 && h[threadIdx.x])
        atomicAdd(&g_hist[threadIdx.x], h[threadIdx.x]);
}

__global__ void k_gpick(int shift, int last)
{
    __shared__ unsigned h[256];
    int tid = threadIdx.x;
    h[tid] = g_hist[tid];
    __syncthreads();
    if (tid == 0) {
        unsigned need = g_state[3], prefix = g_state[0];
        unsigned cum = 0; int b = 255;
        for (; b > 0; b--) { unsigned c = h[b]; if (cum + c >= need) break; cum += c; }
        g_state[0] = prefix | ((unsigned)b << shift);
        g_state[3] = need - cum;
        if (last) {
            unsigned T = g_state[0];
            if (T <= FLIP_ZERO) {
                g_state[1] = FLIP_ZERO; g_state[2] = 0;
                g_state[7] = g_state[5]; g_state[4] = g_state[5];
            } else {
                g_state[1] = T; g_state[2] = g_state[3];
                g_state[7] = EV; g_state[4] = EV - g_state[3];
            }
            g_state[6] = 0;
        }
    }
    g_hist[tid] = 0;
}

__global__ void k_emit_gt()
{
    int i = blockIdx.x * blockDim.x + threadIdx.x;
    if (i >= KM * KM) return;
    unsigned f = fl(g_cand[i]);
    if (f > g_state[1]) {
        unsigned s = atomicAdd(&g_state[6], 1u);
        g_src2[EE + s] = i / KM;
        g_dst2[EE + s] = i - (i / KM) * KM;
        g_mask2[EE + s] = 1.f;
    }
}

__global__ __launch_bounds__(1024)
void k_tiecount()
{
    unsigned T = g_state[1], needT = g_state[2];
    int i = blockIdx.x * 1024 + threadIdx.x;
    int p = (needT > 0) && (i < KM*KM) && (fl(g_cand[i]) == T);
    int c = __syncthreads_count(p);
    if (threadIdx.x == 0) g_tiecnt[blockIdx.x] = (unsigned)c;
}

__global__ __launch_bounds__(1024)
void k_tiescan()
{
    __shared__ unsigned ws[32];
    unsigned run = 0;
    for (int base = 0; base < NBT; base += 1024) {
        int i = base + (int)threadIdx.x;
        unsigned v = (i < NBT) ? g_tiecnt[i] : 0u;
        unsigned incl = blockScanIncl(v, ws);
        if (i < NBT) g_tieoff[i] = run + incl - v;
        unsigned tot = ws[31];
        run += tot;
        __syncthreads();
    }
}

__global__ __launch_bounds__(1024)
void k_emit_tie()
{
    __shared__ unsigned ws[32];
    unsigned T = g_state[1], needT = g_state[2];
    int i = blockIdx.x * 1024 + threadIdx.x;
    unsigned p = (needT > 0) && (i < KM*KM) && (fl(g_cand[i]) == T);
    unsigned incl = blockScanIncl(p, ws);
    unsigned rank = g_tieoff[blockIdx.x] + incl - p;
    if (p && rank < needT) {
        unsigned s = g_state[4] + rank;
        g_src2[EE + s] = i / KM;
        g_dst2[EE + s] = i - (i / KM) * KM;
        g_mask2[EE + s] = 1.f;
    }
}

__global__ void k_fill_dummy()
{
    int t = blockIdx.x * blockDim.x + threadIdx.x;
    if (t >= EV) return;
    if ((unsigned)t >= g_state[7]) {
        g_src2[EE + t] = 0; g_dst2[EE + t] = 0; g_mask2[EE + t] = 0.f;
    }
}

/* ------------------------------ epilogue --------------------------------- */
__global__ void k_hier()
{
    int t = blockIdx.x * blockDim.x + threadIdx.x;
    if (t >= KM * CC) return;
    g_hhier[t] = g_agg2[t] / fmaxf(g_deg2[t >> 6], 1.f) + g_hm[t];
}

__global__ void k_final(float* __restrict__ out)
{
    int t = blockIdx.x * blockDim.x + threadIdx.x;
    if (t >= NN * CC) return;
    int n = t >> 6;
    float mm = g_m[n];
    int j = g_node2m[n];
    float hh = (j >= 0) ? g_hhier[(size_t)j * CC + (t & 63)] : 0.f;
    out[OUT_H + t] = (1.f - mm) * g_hloc[t] + mm * hh;
}

__global__ void k_aux(const float* __restrict__ pos, float* __restrict__ out)
{
    int t = blockIdx.x * blockDim.x + threadIdx.x;
    if (t < NN * 3) out[OUT_POS + t] = pos[t];
    if (t < NN)     out[OUT_M + t]   = g_m[t];
}

/* ------------------------------- launch ---------------------------------- */
extern "C" void kernel_launch(void* const* d_in, const int* in_sizes, int n_in,
                              void* d_out, int out_size)
{
    const float *h=0,*pos=0,*fw1=0,*fb1=0,*fw2=0,*fb2=0,*linw=0;
    const float *mw1=0,*mb1=0,*mw2=0,*mb2=0,*vq=0,*vk=0;
    const int *ei=0;
    int n64 = 0, n36 = 0, n256 = 0;
    for (int i = 0; i < n_in; i++) {
        int s = in_sizes[i]; const void* p = d_in[i];
        if      (s == NN*CC)   h   = (const float*)p;
        else if (s == NN*3)    pos = (const float*)p;
        else if (s == 2*EE)    ei  = (const int*)p;
        else if (s == 8*CC)    fw1 = (const float*)p;
        else if (s == CC*CSH) { if (n36 == 0) fw2 = (const float*)p; else linw = (const float*)p; n36++; }
        else if (s == CSH)     fb2 = (const float*)p;
        else if (s == CC)    { if (n64 == 0) fb1 = (const float*)p;
                               else if (n64 == 1) mb1 = (const float*)p;
                               else mw2 = (const float*)p; n64++; }
        else if (s == SD*64)   mw1 = (const float*)p;
        else if (s == 1)       mb2 = (const float*)p;
        else if (s == SD*SD) { if (n256 == 0) vq = (const float*)p; else vk = (const float*)p; n256++; }
    }
    const int* src = ei;
    const int* dst = ei + EE;
    float* out = (float*)d_out;

    k_clear<<<4096, 256>>>();

    /* conv 1 — chunked gemm1/gemm2 so U stays L2-resident */
    k_geom <<<(EE+255)/256, 256>>>(0, src, dst, pos, fw1, fb1, EE);
    for (int cb = 0; cb < EE; cb += ECH) {
        k_gemm1<<<dim3(ECH/64, 9), 256>>>(0, h, dst, fw2, fb2, cb);
        k_gemm2<<<ECH/64, 256>>>(0, src, linw, cb);
    }
    k_deg  <<<(EE+255)/256, 256>>>(0, src, EE);
    k_update<<<(NN*CC+255)/256, 256>>>(h);
    k_score <<<(NN+127)/128, 128>>>(mw1, mb1, mw2, mb2);

    /* master selection + attention graph */
    k_topk  <<<1, 1024>>>();
    k_master<<<(KM*CC+255)/256, 256>>>(pos);
    k_qk    <<<(KM*32+255)/256, 256>>>(vq, vk);
    k_adjsc <<<(EE+255)/256, 256>>>(src, dst);
    k_attn  <<<dim3((KM+31)/32, (KM+31)/32), dim3(32,32)>>>(out + OUT_A);

    /* exact top-EV over 4M candidates */
    k_ghist<<<1024, 256>>>(24, 1); k_gpick<<<1, 256>>>(24, 0);
    k_ghist<<<1024, 256>>>(16, 0); k_gpick<<<1, 256>>>(16, 0);
    k_ghist<<<1024, 256>>>( 8, 0); k_gpick<<<1, 256>>>( 8, 0);
    k_ghist<<<1024, 256>>>( 0, 0); k_gpick<<<1, 256>>>( 0, 1);
    k_emit_gt  <<<(KM*KM+255)/256, 256>>>();
    k_tiecount <<<NBT, 1024>>>();
    k_tiescan  <<<1, 1024>>>();
    k_emit_tie <<<NBT, 1024>>>();
    k_fill_dummy<<<(EV+255)/256, 256>>>();

    /* conv 2 — chunked as well */
    k_geom <<<(E2+255)/256, 256>>>(1, 0, 0, 0, fw1, fb1, E2);
    for (int cb = 0; cb < E2; cb += ECH) {
        k_gemm1<<<dim3(ECH/64, 9), 256>>>(1, 0, 0, fw2, fb2, cb);
        k_gemm2<<<ECH/64, 256>>>(1, 0, linw, cb);
    }
    k_deg  <<<(E2+255)/256, 256>>>(1, 0, E2);
    k_hier <<<(KM*CC+255)/256, 256>>>();

    /* outputs */
    k_final<<<(NN*CC+255)/256, 256>>>(out);
    k_aux  <<<(NN*3+255)/256, 256>>>(pos, out);
    (void)out_size; (void)n_in;
}

// round 15
// speedup vs baseline: 1.2559x; 1.2559x over previous
#include <cuda_runtime.h>
#include <math.h>
#include <stdint.h>

#define NN   20000
#define EE   160000
#define CC   64
#define SHD  9
#define SD   16
#define KM   2000
#define EV   32000
#define E2   (EE + EV)          /* 192000 */
#define CSH  576
#define FLIP_ZERO 0x80000000u
#define NBT  ((KM*KM + 1023)/1024)   /* 3907 tie-chunks */

#define OUT_H   0
#define OUT_POS 1280000
#define OUT_A   1340000
#define OUT_M   5340000

/* ----------------------------- scratch ----------------------------------- */
static __device__ float g_sh   [(size_t)E2 * SHD];
static __device__ float g_hid  [(size_t)E2 * CC];
static __device__ float g_U    [(size_t)E2 * CSH];
static __device__ float g_agg  [NN * CC];
static __device__ float g_deg  [NN];
static __device__ float g_hloc [NN * CC];
static __device__ float g_score[NN];
static __device__ float g_m    [NN];
static __device__ int   g_master[KM];
static __device__ int   g_node2m[NN];
static __device__ float g_hm   [KM * CC];
static __device__ float g_posm [KM * 3];
static __device__ float g_q    [KM * SD];
static __device__ float g_kk   [KM * SD];
static __device__ float g_adj  [(size_t)KM * KM];
static __device__ float g_cand [(size_t)KM * KM];
static __device__ int   g_src2 [E2];
static __device__ int   g_dst2 [E2];
static __device__ float g_mask2[E2];
static __device__ float g_agg2 [KM * CC];
static __device__ float g_deg2 [KM];
static __device__ float g_hhier[KM * CC];
static __device__ unsigned g_hist[256];
static __device__ unsigned g_tiecnt[NBT];
static __device__ unsigned g_tieoff[NBT];
/* [0]=prefix [1]=T [2]=needTie [3]=need [4]=cntGt [5]=P [6]=emitCtr [7]=totalSel */
static __device__ unsigned g_state[8];

/* ----------------------------- helpers ----------------------------------- */
__device__ __forceinline__ unsigned fl(float x) {
    unsigned u = __float_as_uint(x);
    return (u & 0x80000000u) ? ~u : (u | 0x80000000u);
}
__device__ __forceinline__ float sigm(float x) {
    return (x >= 0.f) ? 1.f / (1.f + expf(-x)) : expf(x) / (1.f + expf(x));
}
/* packed f32x2 helpers (FFMA2 — halves fma-pipe instr; halves are exact FMAs) */
__device__ __forceinline__ unsigned long long pk2(float a) {
    unsigned long long r;
    asm("mov.b64 %0, {%1, %1};" : "=l"(r) : "r"(__float_as_uint(a)));
    return r;
}
__device__ __forceinline__ void fma2(unsigned long long& acc,
                                     unsigned long long a, unsigned long long b) {
    asm("fma.rn.f32x2 %0, %1, %2, %0;" : "+l"(acc) : "l"(a), "l"(b));
}
__device__ __forceinline__ void upk2(unsigned long long v, float& lo, float& hi) {
    unsigned l, h;
    asm("mov.b64 {%0, %1}, %2;" : "=r"(l), "=r"(h) : "l"(v));
    lo = __uint_as_float(l); hi = __uint_as_float(h);
}
__device__ __forceinline__ unsigned blockScanIncl(unsigned v, unsigned* ws) {
    unsigned x = v;
    #pragma unroll
    for (int o = 1; o < 32; o <<= 1) {
        unsigned t = __shfl_up_sync(0xFFFFFFFFu, x, o);
        if ((threadIdx.x & 31) >= o) x += t;
    }
    if ((threadIdx.x & 31) == 31) ws[threadIdx.x >> 5] = x;
    __syncthreads();
    if (threadIdx.x < 32) {
        unsigned w = ws[threadIdx.x];
        #pragma unroll
        for (int o = 1; o < 32; o <<= 1) {
            unsigned t = __shfl_up_sync(0xFFFFFFFFu, w, o);
            if ((int)threadIdx.x >= o) w += t;
        }
        ws[threadIdx.x] = w;
    }
    __syncthreads();
    if (threadIdx.x >= 32) x += ws[(threadIdx.x >> 5) - 1];
    return x;
}

/* ------------------------------ clear ------------------------------------ */
__global__ void k_clear() {
    int i  = blockIdx.x * blockDim.x + threadIdx.x;
    int st = gridDim.x * blockDim.x;
    for (int t = i; t < KM * KM; t += st) g_adj[t] = 0.f;
    for (int t = i; t < NN * CC; t += st) g_agg[t] = 0.f;
    for (int t = i; t < NN;      t += st) g_deg[t] = 0.f;
    for (int t = i; t < KM * CC; t += st) g_agg2[t] = 0.f;
    for (int t = i; t < KM;      t += st) g_deg2[t] = 0.f;
    if (i < 256) g_hist[i] = 0;
    if (i < 8)   g_state[i] = (i == 3) ? (unsigned)EV : 0u;
}

/* --------- geometry: sh + bessel->hidden + degree accumulation ----------- */
__global__ __launch_bounds__(256)
void k_geom(int c2, const int* __restrict__ src, const int* __restrict__ dst,
            const float* __restrict__ pos,
            const float* __restrict__ fw1, const float* __restrict__ fb1, int n)
{
    __shared__ float sw1[8 * CC];
    __shared__ float sb1[CC];
    float* deg = g_deg;
    if (c2) { src = g_src2; dst = g_dst2; pos = g_posm; deg = g_deg2; }
    int tid = threadIdx.x;
    for (int t = tid; t < 8 * CC; t += 256) sw1[t] = fw1[t];
    if (tid < CC) sb1[tid] = fb1[tid];
    __syncthreads();
    int e = blockIdx.x * 256 + tid;
    if (e >= n) return;
    if (c2 && g_mask2[e] == 0.f) return;
    int si = src[e], di = dst[e];
    atomicAdd(&deg[si], 1.f);
    float vx = pos[si*3+0] - pos[di*3+0];
    float vy = pos[si*3+1] - pos[di*3+1];
    float vz = pos[si*3+2] - pos[di*3+2];
    float r  = sqrtf(vx*vx + vy*vy + vz*vz + 1e-12f);
    float iv = 1.0f / r;
    float x = vx*iv, y = vy*iv, z = vz*iv;
    const float s3  = 1.7320508075688772f;
    const float s15 = 3.8729833462074170f;
    const float s5  = 2.2360679774997896f;
    float* so = g_sh + (size_t)e * SHD;
    so[0] = 1.0f;
    so[1] = s3 * x;  so[2] = s3 * y;  so[3] = s3 * z;
    so[4] = s15 * x * y;  so[5] = s15 * y * z;
    so[6] = 0.5f * s5 * (3.0f * z * z - 1.0f);
    so[7] = s15 * x * z;
    so[8] = 0.5f * s15 * (x * x - y * y);
    float rc = fmaxf(r, 1e-9f);
    float u  = fminf(r * 0.2f, 1.0f);
    float u2 = u*u, u4 = u2*u2, u6 = u4*u2;
    float env  = 1.0f - 28.0f*u6 + 48.0f*u6*u - 21.0f*u6*u2;
    float pref = 0.6324555320336759f / rc * env;
    float w0r  = 0.6283185307179586f * r;
    float ef[8];
    #pragma unroll
    for (int nb = 0; nb < 8; nb++) ef[nb] = pref * sinf((float)(nb+1) * w0r);
    float* ho = g_hid + (size_t)e * CC;
    #pragma unroll 4
    for (int o4 = 0; o4 < CC; o4 += 4) {
        float a0 = sb1[o4+0], a1 = sb1[o4+1], a2 = sb1[o4+2], a3 = sb1[o4+3];
        #pragma unroll
        for (int nb = 0; nb < 8; nb++) {
            float efn = ef[nb];
            a0 = fmaf(efn, sw1[nb*CC + o4+0], a0);
            a1 = fmaf(efn, sw1[nb*CC + o4+1], a1);
            a2 = fmaf(efn, sw1[nb*CC + o4+2], a2);
            a3 = fmaf(efn, sw1[nb*CC + o4+3], a3);
        }
        float4 v;
        v.x = fmaxf(a0, 0.f); v.y = fmaxf(a1, 0.f);
        v.z = fmaxf(a2, 0.f); v.w = fmaxf(a3, 0.f);
        *(float4*)(ho + o4) = v;
    }
}

/* ------- GEMM1: U[e,cs] = (hid@fc_w2 + b2) * h[dst,cs/9] * sh[e,cs%9] ----
   A-tile loaded ONCE; 9 n-chunks looped in-block (B reload per chunk).
   Swizzled A-tile + FFMA2. */
__global__ __launch_bounds__(256)
void k_gemm1(int c2, const float* __restrict__ hf, const int* __restrict__ dst,
             const float* __restrict__ w2, const float* __restrict__ b2)
{
    __shared__ float As[64 * 64];
    __shared__ float Bs[64][68];
    if (c2) { hf = g_hm; dst = g_dst2; }
    int eBase = blockIdx.x * 64;
    int tid = threadIdx.x;
    if (c2) {
        int p = (tid < 64) ? (g_mask2[eBase + tid] != 0.f) : 0;
        if (__syncthreads_count(p) == 0) return;
    }
    int lr = tid >> 4, t4 = tid & 15, lc4 = t4 * 4;
    #pragma unroll
    for (int rep = 0; rep < 4; rep++) {
        int row = lr + rep * 16;
        float4 a = *(const float4*)(g_hid + (size_t)(eBase + row) * CC + lc4);
        int sw = (((row >> 2) ^ t4) << 2) + (row & 3);
        As[(lc4+0)*64 + sw] = a.x;
        As[(lc4+1)*64 + sw] = a.y;
        As[(lc4+2)*64 + sw] = a.z;
        As[(lc4+3)*64 + sw] = a.w;
    }
    int ty = tid >> 4, tx = tid & 15;
    for (int nb = 0; nb < 9; nb++) {
        int nBase = nb * 64;
        #pragma unroll
        for (int rep = 0; rep < 4; rep++) {
            int row = lr + rep * 16;
            *(float4*)&Bs[row][lc4] =
                *(const float4*)(w2 + (size_t)row * CSH + nBase + lc4);
        }
        __syncthreads();
        unsigned long long acc[4][2] = {};
        #pragma unroll 8
        for (int k = 0; k < 64; k++) {
            float4 a4 = *(const float4*)&As[k*64 + ((ty ^ (k >> 2)) << 2)];
            ulonglong2 bv = *(const ulonglong2*)&Bs[k][tx*4];
            unsigned long long a0 = pk2(a4.x), a1 = pk2(a4.y);
            unsigned long long a2 = pk2(a4.z), a3 = pk2(a4.w);
            fma2(acc[0][0], a0, bv.x); fma2(acc[0][1], a0, bv.y);
            fma2(acc[1][0], a1, bv.x); fma2(acc[1][1], a1, bv.y);
            fma2(acc[2][0], a2, bv.x); fma2(acc[2][1], a2, bv.y);
            fma2(acc[3][0], a3, bv.x); fma2(acc[3][1], a3, bv.y);
        }
        #pragma unroll
        for (int i = 0; i < 4; i++) {
            int e = eBase + ty*4 + i;
            int d = dst[e];
            const float* he = hf + (size_t)d * CC;
            const float* se = g_sh + (size_t)e * SHD;
            int cs0 = nBase + tx*4;
            float av[4];
            upk2(acc[i][0], av[0], av[1]);
            upk2(acc[i][1], av[2], av[3]);
            float4 o;
            {
                int cs = cs0+0; int c = cs/9, s = cs - c*9;
                o.x = (av[0] + b2[cs]) * he[c] * se[s];
            }{
                int cs = cs0+1; int c = cs/9, s = cs - c*9;
                o.y = (av[1] + b2[cs]) * he[c] * se[s];
            }{
                int cs = cs0+2; int c = cs/9, s = cs - c*9;
                o.z = (av[2] + b2[cs]) * he[c] * se[s];
            }{
                int cs = cs0+3; int c = cs/9, s = cs - c*9;
                o.w = (av[3] + b2[cs]) * he[c] * se[s];
            }
            *(float4*)(g_U + (size_t)e * CSH + cs0) = o;
        }
        __syncthreads();   /* Bs reads done before next chunk's overwrite */
    }
}

/* ----------- GEMM2: msg = U @ lin_w ; atomic scatter by src -------------- */
__global__ __launch_bounds__(256)
void k_gemm2(int c2, const int* __restrict__ src, const float* __restrict__ lw)
{
    __shared__ float As[64 * 64];
    __shared__ float Bs[64][68];
    const float* msk = 0;
    float* agg = g_agg;
    if (c2) { src = g_src2; msk = g_mask2; agg = g_agg2; }
    int eBase = blockIdx.x * 64;
    int tid = threadIdx.x;
    if (c2) {
        int p = (tid < 64) ? (g_mask2[eBase + tid] != 0.f) : 0;
        if (__syncthreads_count(p) == 0) return;
    }
    int lr = tid >> 4, t4 = tid & 15, lc4 = t4 * 4;
    int ty = tid >> 4, tx = tid & 15;
    unsigned long long acc[4][2] = {};
    for (int kt = 0; kt < 9; kt++) {
        #pragma unroll
        for (int rep = 0; rep < 4; rep++) {
            int row = lr + rep * 16;
            float4 a = *(const float4*)(g_U + (size_t)(eBase + row) * CSH + kt*64 + lc4);
            int sw = (((row >> 2) ^ t4) << 2) + (row & 3);
            As[(lc4+0)*64 + sw] = a.x;
            As[(lc4+1)*64 + sw] = a.y;
            As[(lc4+2)*64 + sw] = a.z;
            As[(lc4+3)*64 + sw] = a.w;
            float4 b = *(const float4*)(lw + (size_t)(kt*64 + row) * CC + lc4);
            *(float4*)&Bs[row][lc4] = b;
        }
        __syncthreads();
        #pragma unroll 8
        for (int k = 0; k < 64; k++) {
            float4 a4 = *(const float4*)&As[k*64 + ((ty ^ (k >> 2)) << 2)];
            ulonglong2 bv = *(const ulonglong2*)&Bs[k][tx*4];
            unsigned long long a0 = pk2(a4.x), a1 = pk2(a4.y);
            unsigned long long a2 = pk2(a4.z), a3 = pk2(a4.w);
            fma2(acc[0][0], a0, bv.x); fma2(acc[0][1], a0, bv.y);
            fma2(acc[1][0], a1, bv.x); fma2(acc[1][1], a1, bv.y);
            fma2(acc[2][0], a2, bv.x); fma2(acc[2][1], a2, bv.y);
            fma2(acc[3][0], a3, bv.x); fma2(acc[3][1], a3, bv.y);
        }
        __syncthreads();
    }
    #pragma unroll
    for (int i = 0; i < 4; i++) {
        int e = eBase + ty*4 + i;
        float mm = msk ? msk[e] : 1.f;
        if (mm != 0.f) {
            int s = src[e];
            float av[4];
            upk2(acc[i][0], av[0], av[1]);
            upk2(acc[i][1], av[2], av[3]);
            float* ap = agg + (size_t)s * CC + tx*4;
            atomicAdd(ap+0, av[0]);
            atomicAdd(ap+1, av[1]);
            atomicAdd(ap+2, av[2]);
            atomicAdd(ap+3, av[3]);
        }
    }
}

/* ------------------------- h_local + score MLP --------------------------- */
__global__ void k_update(const float* __restrict__ h)
{
    int t = blockIdx.x * blockDim.x + threadIdx.x;
    if (t >= NN * CC) return;
    int n = t >> 6;
    g_hloc[t] = g_agg[t] / fmaxf(g_deg[n], 1.f) + h[t];
}

__global__ __launch_bounds__(128)
void k_score(const float* __restrict__ w1, const float* __restrict__ b1,
             const float* __restrict__ w2, const float* __restrict__ b2)
{
    __shared__ float sw1[SD * 64];
    __shared__ float sb1[64];
    __shared__ float sw2[64];
    int tid = threadIdx.x;
    for (int t = tid; t < SD*64; t += 128) sw1[t] = w1[t];
    if (tid < 64) { sb1[tid] = b1[tid]; sw2[tid] = w2[tid]; }
    __syncthreads();
    int i = blockIdx.x * 128 + tid;
    if (i >= NN) return;
    float hs[SD];
    #pragma unroll
    for (int c = 0; c < SD; c++) hs[c] = g_hloc[(size_t)i * CC + c];
    float sum = 0.f;
    for (int j = 0; j < 64; j++) {
        float a = sb1[j];
        #pragma unroll
        for (int c = 0; c < SD; c++) a = fmaf(hs[c], sw1[c*64 + j], a);
        sum = fmaf(fmaxf(a, 0.f), sw2[j], sum);
    }
    g_score[i] = sigm(sum + b2[0]);
}

/* -------- exact top-K of scores (desc value, asc index tie-break) -------- */
__global__ __launch_bounds__(1024)
void k_topk()
{
    __shared__ unsigned hist[256];
    __shared__ unsigned ws[32];
    __shared__ unsigned sPre, sNeed;
    int tid = threadIdx.x;
    unsigned prefix = 0, need = KM;
    for (int round = 0; round < 4; round++) {
        int shift = 24 - 8*round;
        if (tid < 256) hist[tid] = 0;
        __syncthreads();
        for (int i = tid; i < NN; i += 1024) {
            unsigned f = fl(g_score[i]);
            if (round == 0 || (f >> (shift+8)) == (prefix >> (shift+8)))
                atomicAdd(&hist[(f >> shift) & 255], 1u);
        }
        __syncthreads();
        if (tid == 0) {
            unsigned cum = 0; int b = 255;
            for (; b > 0; b--) { unsigned c = hist[b]; if (cum + c >= need) break; cum += c; }
            sPre = prefix | ((unsigned)b << shift);
            sNeed = need - cum;
        }
        __syncthreads();
        prefix = sPre; need = sNeed;
        __syncthreads();
    }
    unsigned T = prefix, needTie = need;
    unsigned runSel = 0, runTie = 0;
    for (int base = 0; base < NN; base += 1024) {
        int i = base + tid;
        int valid = i < NN;
        float sc = valid ? g_score[i] : 0.f;
        unsigned f = valid ? fl(sc) : 0u;
        unsigned isGt  = (valid && f >  T) ? 1u : 0u;
        unsigned isTie = (valid && f == T) ? 1u : 0u;
        unsigned pk = isGt | (isTie << 16);
        unsigned incl = blockScanIncl(pk, ws);
        unsigned excl = incl - pk;
        unsigned gtE = excl & 0xFFFFu, tieE = excl >> 16;
        unsigned remTie = (needTie > runTie) ? needTie - runTie : 0u;
        int take = isGt || (isTie && tieE < remTie);
        unsigned rank = runSel + gtE + (tieE < remTie ? tieE : remTie);
        if (valid) {
            if (take) { g_master[rank] = i; g_node2m[i] = (int)rank; g_m[i] = sc; }
            else      { g_node2m[i] = -1;   g_m[i] = 0.f; }
        }
        unsigned tot = ws[31];
        unsigned totGt = tot & 0xFFFFu, totTie = tot >> 16;
        runSel += totGt + (totTie < remTie ? totTie : remTie);
        runTie += totTie;
        __syncthreads();
    }
}

/* ----------------------- master gather + q/k ----------------------------- */
__global__ void k_master(const float* __restrict__ pos)
{
    int t = blockIdx.x * blockDim.x + threadIdx.x;
    if (t < KM * CC) {
        int j = t >> 6, c = t & 63;
        g_hm[t] = g_hloc[(size_t)g_master[j] * CC + c];
    }
    if (t < KM * 3) {
        g_posm[t] = pos[(size_t)g_master[t/3] * 3 + (t - (t/3)*3)];
    }
}

__global__ void k_qk(const float* __restrict__ wq, const float* __restrict__ wk)
{
    int t = blockIdx.x * blockDim.x + threadIdx.x;
    if (t >= KM * 32) return;
    int j = t >> 5, u = t & 31;
    const float* hm = g_hm + (size_t)j * CC;
    if (u < 16) {
        float a = 0.f;
        #pragma unroll
        for (int i = 0; i < SD; i++) a = fmaf(hm[i], wq[i*SD + u], a);
        g_q[j*SD + u] = a;
    } else {
        int uu = u - 16;
        float a = 0.f;
        #pragma unroll
        for (int i = 0; i < SD; i++) a = fmaf(hm[i], wk[i*SD + uu], a);
        g_kk[j*SD + uu] = a;
    }
}

/* ----------------- adjacency scatter + master edge remap ----------------- */
__global__ void k_adjsc(const int* __restrict__ src, const int* __restrict__ dst)
{
    int e = blockIdx.x * blockDim.x + threadIdx.x;
    if (e >= EE) return;
    int sm = g_node2m[src[e]], dm = g_node2m[dst[e]];
    int ok = (sm >= 0) && (dm >= 0);
    g_src2[e] = sm >= 0 ? sm : 0;
    g_dst2[e] = dm >= 0 ? dm : 0;
    g_mask2[e] = ok ? 1.f : 0.f;
    if (ok) atomicAdd(&g_adj[(size_t)sm * KM + dm], 1.f);
}

/* ------------------- attention + A_virtual + candidates ------------------ */
__global__ __launch_bounds__(1024)
void k_attn(float* __restrict__ outA)
{
    __shared__ float qt[32][16];
    __shared__ float kt[32][17];
    int j0 = blockIdx.x * 32, i0 = blockIdx.y * 32;
    int tx = threadIdx.x, ty = threadIdx.y;
    int i = i0 + ty, j = j0 + tx;
    if (tx < 16) {
        qt[ty][tx] = (i < KM) ? g_q[(size_t)i*SD + tx] : 0.f;
        kt[ty][tx] = (j0 + ty < KM) ? g_kk[(size_t)(j0+ty)*SD + tx] : 0.f;
    }
    __syncthreads();
    int p = 0;
    if (i < KM && j < KM) {
        float d = 0.f;
        #pragma unroll
        for (int t = 0; t < SD; t++) d = fmaf(qt[ty][t], kt[tx][t], d);
        float at = sigm(d * 0.25f);
        bool exist = (g_adj[(size_t)i*KM + j] > 0.f) || (i == j);
        float av = (!exist && at > 0.5f) ? 1.f : 0.f;
        outA[(size_t)i*KM + j] = av;
        float cd = av * at;
        g_cand[(size_t)i*KM + j] = cd;
        p = cd > 0.f;
    }
    int cnt = __syncthreads_count(p);
    if (tx == 0 && ty == 0 && cnt) atomicAdd(&g_state[5], (unsigned)cnt);
}

/* ----------------- global radix select for top-E_V edges ----------------- */
__global__ __launch_bounds__(256)
void k_ghist(int shift, int first)
{
    __shared__ unsigned h[256];
    if (threadIdx.x < 256) h[threadIdx.x] = 0;
    __syncthreads();
    unsigned prefix = g_state[0];
    int n = KM * KM;
    for (int i = blockIdx.x * blockDim.x + threadIdx.x; i < n;
         i += gridDim.x * blockDim.x) {
        unsigned f = fl(g_cand[i]);
        if (first || (f >> (shift+8)) == (prefix >> (shift+8)))
            atomicAdd(&h[(f >> shift) & 255], 1u);
    }
    __syncthreads();
    if (threadIdx.x < 256 && h[threadIdx.x])
        atomicAdd(&g_hist[threadIdx.x], h[threadIdx.x]);
}

__global__ void k_gpick(int shift, int last)
{
    __shared__ unsigned h[256];
    int tid = threadIdx.x;
    h[tid] = g_hist[tid];
    __syncthreads();
    if (tid == 0) {
        unsigned need = g_state[3], prefix = g_state[0];
        unsigned cum = 0; int b = 255;
        for (; b > 0; b--) { unsigned c = h[b]; if (cum + c >= need) break; cum += c; }
        g_state[0] = prefix | ((unsigned)b << shift);
        g_state[3] = need - cum;
        if (last) {
            unsigned T = g_state[0];
            if (T <= FLIP_ZERO) {
                g_state[1] = FLIP_ZERO; g_state[2] = 0;
                g_state[7] = g_state[5]; g_state[4] = g_state[5];
            } else {
                g_state[1] = T; g_state[2] = g_state[3];
                g_state[7] = EV; g_state[4] = EV - g_state[3];
            }
            g_state[6] = 0;
        }
    }
    g_hist[tid] = 0;
}

__global__ void k_emit_gt()
{
    int i = blockIdx.x * blockDim.x + threadIdx.x;
    if (i >= KM * KM) return;
    unsigned f = fl(g_cand[i]);
    if (f > g_state[1]) {
        unsigned s = atomicAdd(&g_state[6], 1u);
        g_src2[EE + s] = i / KM;
        g_dst2[EE + s] = i - (i / KM) * KM;
        g_mask2[EE + s] = 1.f;
    }
}

__global__ __launch_bounds__(1024)
void k_tiecount()
{
    unsigned T = g_state[1], needT = g_state[2];
    int i = blockIdx.x * 1024 + threadIdx.x;
    int p = (needT > 0) && (i < KM*KM) && (fl(g_cand[i]) == T);
    int c = __syncthreads_count(p);
    if (threadIdx.x == 0) g_tiecnt[blockIdx.x] = (unsigned)c;
}

__global__ __launch_bounds__(1024)
void k_tiescan()
{
    __shared__ unsigned ws[32];
    unsigned run = 0;
    for (int base = 0; base < NBT; base += 1024) {
        int i = base + (int)threadIdx.x;
        unsigned v = (i < NBT) ? g_tiecnt[i] : 0u;
        unsigned incl = blockScanIncl(v, ws);
        if (i < NBT) g_tieoff[i] = run + incl - v;
        unsigned tot = ws[31];
        run += tot;
        __syncthreads();
    }
}

__global__ __launch_bounds__(1024)
void k_emit_tie()
{
    __shared__ unsigned ws[32];
    unsigned T = g_state[1], needT = g_state[2];
    int i = blockIdx.x * 1024 + threadIdx.x;
    unsigned p = (needT > 0) && (i < KM*KM) && (fl(g_cand[i]) == T);
    unsigned incl = blockScanIncl(p, ws);
    unsigned rank = g_tieoff[blockIdx.x] + incl - p;
    if (p && rank < needT) {
        unsigned s = g_state[4] + rank;
        g_src2[EE + s] = i / KM;
        g_dst2[EE + s] = i - (i / KM) * KM;
        g_mask2[EE + s] = 1.f;
    }
}

__global__ void k_fill_dummy()
{
    int t = blockIdx.x * blockDim.x + threadIdx.x;
    if (t >= EV) return;
    if ((unsigned)t >= g_state[7]) {
        g_src2[EE + t] = 0; g_dst2[EE + t] = 0; g_mask2[EE + t] = 0.f;
    }
}

/* ------------------------------ epilogue --------------------------------- */
__global__ void k_hier()
{
    int t = blockIdx.x * blockDim.x + threadIdx.x;
    if (t >= KM * CC) return;
    g_hhier[t] = g_agg2[t] / fmaxf(g_deg2[t >> 6], 1.f) + g_hm[t];
}

__global__ void k_final(float* __restrict__ out)
{
    int t = blockIdx.x * blockDim.x + threadIdx.x;
    if (t >= NN * CC) return;
    int n = t >> 6;
    float mm = g_m[n];
    int j = g_node2m[n];
    float hh = (j >= 0) ? g_hhier[(size_t)j * CC + (t & 63)] : 0.f;
    out[OUT_H + t] = (1.f - mm) * g_hloc[t] + mm * hh;
}

__global__ void k_aux(const float* __restrict__ pos, float* __restrict__ out)
{
    int t = blockIdx.x * blockDim.x + threadIdx.x;
    if (t < NN * 3) out[OUT_POS + t] = pos[t];
    if (t < NN)     out[OUT_M + t]   = g_m[t];
}

/* ------------------------------- launch ---------------------------------- */
extern "C" void kernel_launch(void* const* d_in, const int* in_sizes, int n_in,
                              void* d_out, int out_size)
{
    const float *h=0,*pos=0,*fw1=0,*fb1=0,*fw2=0,*fb2=0,*linw=0;
    const float *mw1=0,*mb1=0,*mw2=0,*mb2=0,*vq=0,*vk=0;
    const int *ei=0;
    int n64 = 0, n36 = 0, n256 = 0;
    for (int i = 0; i < n_in; i++) {
        int s = in_sizes[i]; const void* p = d_in[i];
        if      (s == NN*CC)   h   = (const float*)p;
        else if (s == NN*3)    pos = (const float*)p;
        else if (s == 2*EE)    ei  = (const int*)p;
        else if (s == 8*CC)    fw1 = (const float*)p;
        else if (s == CC*CSH) { if (n36 == 0) fw2 = (const float*)p; else linw = (const float*)p; n36++; }
        else if (s == CSH)     fb2 = (const float*)p;
        else if (s == CC)    { if (n64 == 0) fb1 = (const float*)p;
                               else if (n64 == 1) mb1 = (const float*)p;
                               else mw2 = (const float*)p; n64++; }
        else if (s == SD*64)   mw1 = (const float*)p;
        else if (s == 1)       mb2 = (const float*)p;
        else if (s == SD*SD) { if (n256 == 0) vq = (const float*)p; else vk = (const float*)p; n256++; }
    }
    const int* src = ei;
    const int* dst = ei + EE;
    float* out = (float*)d_out;

    k_clear<<<4096, 256>>>();

    /* conv 1 on the full graph */
    k_geom <<<(EE+255)/256, 256>>>(0, src, dst, pos, fw1, fb1, EE);
    k_gemm1<<<EE/64, 256>>>(0, h, dst, fw2, fb2);
    k_gemm2<<<EE/64, 256>>>(0, src, linw);
    k_update<<<(NN*CC+255)/256, 256>>>(h);
    k_score <<<(NN+127)/128, 128>>>(mw1, mb1, mw2, mb2);

    /* master selection + attention graph */
    k_topk  <<<1, 1024>>>();
    k_master<<<(KM*CC+255)/256, 256>>>(pos);
    k_qk    <<<(KM*32+255)/256, 256>>>(vq, vk);
    k_adjsc <<<(EE+255)/256, 256>>>(src, dst);
    k_attn  <<<dim3((KM+31)/32, (KM+31)/32), dim3(32,32)>>>(out + OUT_A);

    /* exact top-EV over 4M candidates */
    k_ghist<<<1024, 256>>>(24, 1); k_gpick<<<1, 256>>>(24, 0);
    k_ghist<<<1024, 256>>>(16, 0); k_gpick<<<1, 256>>>(16, 0);
    k_ghist<<<1024, 256>>>( 8, 0); k_gpick<<<1, 256>>>( 8, 0);
    k_ghist<<<1024, 256>>>( 0, 0); k_gpick<<<1, 256>>>( 0, 1);
    k_emit_gt  <<<(KM*KM+255)/256, 256>>>();
    k_tiecount <<<NBT, 1024>>>();
    k_tiescan  <<<1, 1024>>>();
    k_emit_tie <<<NBT, 1024>>>();
    k_fill_dummy<<<(EV+255)/256, 256>>>();

    /* conv 2 on the master graph (real + virtual edges) */
    k_geom <<<(E2+255)/256, 256>>>(1, 0, 0, 0, fw1, fb1, E2);
    k_gemm1<<<E2/64, 256>>>(1, 0, 0, fw2, fb2);
    k_gemm2<<<E2/64, 256>>>(1, 0, linw);
    k_hier <<<(KM*CC+255)/256, 256>>>();

    /* outputs */
    k_final<<<(NN*CC+255)/256, 256>>>(out);
    k_aux  <<<(NN*3+255)/256, 256>>>(pos, out);
    (void)out_size; (void)n_in;
}

// round 16
// speedup vs baseline: 1.2617x; 1.0046x over previous
#include <cuda_runtime.h>
#include <math.h>
#include <stdint.h>

#define NN   20000
#define EE   160000
#define CC   64
#define SHD  9
#define SD   16
#define KM   2000
#define EV   32000
#define E2   (EE + EV)          /* 192000 */
#define CSH  576
#define FLIP_ZERO 0x80000000u
#define NBT  ((KM*KM + 1023)/1024)   /* 3907 tie-chunks */

#define OUT_H   0
#define OUT_POS 1280000
#define OUT_A   1340000
#define OUT_M   5340000

/* ----------------------------- scratch ----------------------------------- */
static __device__ float g_sh   [(size_t)E2 * SHD];
static __device__ float g_hid  [(size_t)E2 * CC];
static __device__ float g_U    [(size_t)E2 * CSH];
static __device__ float g_agg  [NN * CC];
static __device__ float g_deg  [NN];
static __device__ float g_hloc [NN * CC];
static __device__ float g_score[NN];
static __device__ float g_m    [NN];
static __device__ int   g_master[KM];
static __device__ int   g_node2m[NN];
static __device__ float g_hm   [KM * CC];
static __device__ float g_posm [KM * 3];
static __device__ float g_q    [KM * SD];
static __device__ float g_kk   [KM * SD];
static __device__ float g_adj  [(size_t)KM * KM];
static __device__ float g_cand [(size_t)KM * KM];
static __device__ int   g_src2 [E2];
static __device__ int   g_dst2 [E2];
static __device__ float g_mask2[E2];
static __device__ float g_agg2 [KM * CC];
static __device__ float g_deg2 [KM];
static __device__ float g_hhier[KM * CC];
static __device__ unsigned g_hist[256];
static __device__ unsigned g_tiecnt[NBT];
static __device__ unsigned g_tieoff[NBT];
/* [0]=prefix [1]=T [2]=needTie [3]=need [4]=cntGt [5]=P [6]=emitCtr [7]=totalSel */
static __device__ unsigned g_state[8];

/* ----------------------------- helpers ----------------------------------- */
__device__ __forceinline__ unsigned fl(float x) {
    unsigned u = __float_as_uint(x);
    return (u & 0x80000000u) ? ~u : (u | 0x80000000u);
}
__device__ __forceinline__ float sigm(float x) {
    return (x >= 0.f) ? 1.f / (1.f + expf(-x)) : expf(x) / (1.f + expf(x));
}
/* packed f32x2 helpers (FFMA2 — halves fma-pipe instr; halves are exact FMAs) */
__device__ __forceinline__ unsigned long long pk2(float a) {
    unsigned long long r;
    asm("mov.b64 %0, {%1, %1};" : "=l"(r) : "r"(__float_as_uint(a)));
    return r;
}
__device__ __forceinline__ void fma2(unsigned long long& acc,
                                     unsigned long long a, unsigned long long b) {
    asm("fma.rn.f32x2 %0, %1, %2, %0;" : "+l"(acc) : "l"(a), "l"(b));
}
__device__ __forceinline__ void upk2(unsigned long long v, float& lo, float& hi) {
    unsigned l, h;
    asm("mov.b64 {%0, %1}, %2;" : "=r"(l), "=r"(h) : "l"(v));
    lo = __uint_as_float(l); hi = __uint_as_float(h);
}
__device__ __forceinline__ unsigned blockScanIncl(unsigned v, unsigned* ws) {
    unsigned x = v;
    #pragma unroll
    for (int o = 1; o < 32; o <<= 1) {
        unsigned t = __shfl_up_sync(0xFFFFFFFFu, x, o);
        if ((threadIdx.x & 31) >= o) x += t;
    }
    if ((threadIdx.x & 31) == 31) ws[threadIdx.x >> 5] = x;
    __syncthreads();
    if (threadIdx.x < 32) {
        unsigned w = ws[threadIdx.x];
        #pragma unroll
        for (int o = 1; o < 32; o <<= 1) {
            unsigned t = __shfl_up_sync(0xFFFFFFFFu, w, o);
            if ((int)threadIdx.x >= o) w += t;
        }
        ws[threadIdx.x] = w;
    }
    __syncthreads();
    if (threadIdx.x >= 32) x += ws[(threadIdx.x >> 5) - 1];
    return x;
}

/* ------------------------------ clear ------------------------------------ */
__global__ void k_clear() {
    int i  = blockIdx.x * blockDim.x + threadIdx.x;
    int st = gridDim.x * blockDim.x;
    for (int t = i; t < KM * KM; t += st) g_adj[t] = 0.f;
    for (int t = i; t < NN * CC; t += st) g_agg[t] = 0.f;
    for (int t = i; t < NN;      t += st) g_deg[t] = 0.f;
    for (int t = i; t < KM * CC; t += st) g_agg2[t] = 0.f;
    for (int t = i; t < KM;      t += st) g_deg2[t] = 0.f;
    if (i < 256) g_hist[i] = 0;
    if (i < 8)   g_state[i] = (i == 3) ? (unsigned)EV : 0u;
}

/* --------- geometry: sh + bessel->hidden + degree accumulation ----------- */
__global__ __launch_bounds__(256)
void k_geom(int c2, const int* __restrict__ src, const int* __restrict__ dst,
            const float* __restrict__ pos,
            const float* __restrict__ fw1, const float* __restrict__ fb1, int n)
{
    __shared__ float sw1[8 * CC];
    __shared__ float sb1[CC];
    float* deg = g_deg;
    if (c2) { src = g_src2; dst = g_dst2; pos = g_posm; deg = g_deg2; }
    int tid = threadIdx.x;
    for (int t = tid; t < 8 * CC; t += 256) sw1[t] = fw1[t];
    if (tid < CC) sb1[tid] = fb1[tid];
    __syncthreads();
    int e = blockIdx.x * 256 + tid;
    if (e >= n) return;
    if (c2 && g_mask2[e] == 0.f) return;
    int si = src[e], di = dst[e];
    atomicAdd(&deg[si], 1.f);
    float vx = pos[si*3+0] - pos[di*3+0];
    float vy = pos[si*3+1] - pos[di*3+1];
    float vz = pos[si*3+2] - pos[di*3+2];
    float r  = sqrtf(vx*vx + vy*vy + vz*vz + 1e-12f);
    float iv = 1.0f / r;
    float x = vx*iv, y = vy*iv, z = vz*iv;
    const float s3  = 1.7320508075688772f;
    const float s15 = 3.8729833462074170f;
    const float s5  = 2.2360679774997896f;
    float* so = g_sh + (size_t)e * SHD;
    so[0] = 1.0f;
    so[1] = s3 * x;  so[2] = s3 * y;  so[3] = s3 * z;
    so[4] = s15 * x * y;  so[5] = s15 * y * z;
    so[6] = 0.5f * s5 * (3.0f * z * z - 1.0f);
    so[7] = s15 * x * z;
    so[8] = 0.5f * s15 * (x * x - y * y);
    float rc = fmaxf(r, 1e-9f);
    float u  = fminf(r * 0.2f, 1.0f);
    float u2 = u*u, u4 = u2*u2, u6 = u4*u2;
    float env  = 1.0f - 28.0f*u6 + 48.0f*u6*u - 21.0f*u6*u2;
    float pref = 0.6324555320336759f / rc * env;
    float w0r  = 0.6283185307179586f * r;
    float ef[8];
    #pragma unroll
    for (int nb = 0; nb < 8; nb++) ef[nb] = pref * sinf((float)(nb+1) * w0r);
    float* ho = g_hid + (size_t)e * CC;
    #pragma unroll 4
    for (int o4 = 0; o4 < CC; o4 += 4) {
        float a0 = sb1[o4+0], a1 = sb1[o4+1], a2 = sb1[o4+2], a3 = sb1[o4+3];
        #pragma unroll
        for (int nb = 0; nb < 8; nb++) {
            float efn = ef[nb];
            a0 = fmaf(efn, sw1[nb*CC + o4+0], a0);
            a1 = fmaf(efn, sw1[nb*CC + o4+1], a1);
            a2 = fmaf(efn, sw1[nb*CC + o4+2], a2);
            a3 = fmaf(efn, sw1[nb*CC + o4+3], a3);
        }
        float4 v;
        v.x = fmaxf(a0, 0.f); v.y = fmaxf(a1, 0.f);
        v.z = fmaxf(a2, 0.f); v.w = fmaxf(a3, 0.f);
        *(float4*)(ho + o4) = v;
    }
}

/* ------- GEMM1: U[e,cs] = (hid@fc_w2 + b2) * h[dst,cs/9] * sh[e,cs%9] ----
   A-tile loaded ONCE; 9 n-chunks looped in-block. Swizzled A + FFMA2. */
__global__ __launch_bounds__(256)
void k_gemm1(int c2, const float* __restrict__ hf, const int* __restrict__ dst,
             const float* __restrict__ w2, const float* __restrict__ b2)
{
    __shared__ float As[64 * 64];
    __shared__ float Bs[64][68];
    if (c2) { hf = g_hm; dst = g_dst2; }
    int eBase = blockIdx.x * 64;
    int tid = threadIdx.x;
    if (c2) {
        int p = (tid < 64) ? (g_mask2[eBase + tid] != 0.f) : 0;
        if (__syncthreads_count(p) == 0) return;
    }
    int lr = tid >> 4, t4 = tid & 15, lc4 = t4 * 4;
    #pragma unroll
    for (int rep = 0; rep < 4; rep++) {
        int row = lr + rep * 16;
        float4 a = *(const float4*)(g_hid + (size_t)(eBase + row) * CC + lc4);
        int sw = (((row >> 2) ^ t4) << 2) + (row & 3);
        As[(lc4+0)*64 + sw] = a.x;
        As[(lc4+1)*64 + sw] = a.y;
        As[(lc4+2)*64 + sw] = a.z;
        As[(lc4+3)*64 + sw] = a.w;
    }
    int ty = tid >> 4, tx = tid & 15;
    for (int nb = 0; nb < 9; nb++) {
        int nBase = nb * 64;
        #pragma unroll
        for (int rep = 0; rep < 4; rep++) {
            int row = lr + rep * 16;
            *(float4*)&Bs[row][lc4] =
                *(const float4*)(w2 + (size_t)row * CSH + nBase + lc4);
        }
        __syncthreads();
        unsigned long long acc[4][2] = {};
        #pragma unroll 8
        for (int k = 0; k < 64; k++) {
            float4 a4 = *(const float4*)&As[k*64 + ((ty ^ (k >> 2)) << 2)];
            ulonglong2 bv = *(const ulonglong2*)&Bs[k][tx*4];
            unsigned long long a0 = pk2(a4.x), a1 = pk2(a4.y);
            unsigned long long a2 = pk2(a4.z), a3 = pk2(a4.w);
            fma2(acc[0][0], a0, bv.x); fma2(acc[0][1], a0, bv.y);
            fma2(acc[1][0], a1, bv.x); fma2(acc[1][1], a1, bv.y);
            fma2(acc[2][0], a2, bv.x); fma2(acc[2][1], a2, bv.y);
            fma2(acc[3][0], a3, bv.x); fma2(acc[3][1], a3, bv.y);
        }
        #pragma unroll
        for (int i = 0; i < 4; i++) {
            int e = eBase + ty*4 + i;
            int d = dst[e];
            const float* he = hf + (size_t)d * CC;
            const float* se = g_sh + (size_t)e * SHD;
            int cs0 = nBase + tx*4;
            float av[4];
            upk2(acc[i][0], av[0], av[1]);
            upk2(acc[i][1], av[2], av[3]);
            float4 o;
            {
                int cs = cs0+0; int c = cs/9, s = cs - c*9;
                o.x = (av[0] + b2[cs]) * he[c] * se[s];
            }{
                int cs = cs0+1; int c = cs/9, s = cs - c*9;
                o.y = (av[1] + b2[cs]) * he[c] * se[s];
            }{
                int cs = cs0+2; int c = cs/9, s = cs - c*9;
                o.z = (av[2] + b2[cs]) * he[c] * se[s];
            }{
                int cs = cs0+3; int c = cs/9, s = cs - c*9;
                o.w = (av[3] + b2[cs]) * he[c] * se[s];
            }
            *(float4*)(g_U + (size_t)e * CSH + cs0) = o;
        }
        __syncthreads();   /* Bs reads done before next chunk's overwrite */
    }
}

/* ----------- GEMM2: msg = U @ lin_w ; atomic scatter by src --------------
   U-stream software-prefetched into registers: STS comes from resident regs,
   next kt's DRAM loads overlap the inner FMA loop. Bit-identical math. */
__global__ __launch_bounds__(256)
void k_gemm2(int c2, const int* __restrict__ src, const float* __restrict__ lw)
{
    __shared__ float As[64 * 64];
    __shared__ float Bs[64][68];
    const float* msk = 0;
    float* agg = g_agg;
    if (c2) { src = g_src2; msk = g_mask2; agg = g_agg2; }
    int eBase = blockIdx.x * 64;
    int tid = threadIdx.x;
    if (c2) {
        int p = (tid < 64) ? (g_mask2[eBase + tid] != 0.f) : 0;
        if (__syncthreads_count(p) == 0) return;
    }
    int lr = tid >> 4, t4 = tid & 15, lc4 = t4 * 4;
    int ty = tid >> 4, tx = tid & 15;
    unsigned long long acc[4][2] = {};
    float4 pa[4];
    #pragma unroll
    for (int rep = 0; rep < 4; rep++) {
        int row = lr + rep * 16;
        pa[rep] = *(const float4*)(g_U + (size_t)(eBase + row) * CSH + lc4);
    }
    for (int kt = 0; kt < 9; kt++) {
        #pragma unroll
        for (int rep = 0; rep < 4; rep++) {
            int row = lr + rep * 16;
            float4 a = pa[rep];
            int sw = (((row >> 2) ^ t4) << 2) + (row & 3);
            As[(lc4+0)*64 + sw] = a.x;
            As[(lc4+1)*64 + sw] = a.y;
            As[(lc4+2)*64 + sw] = a.z;
            As[(lc4+3)*64 + sw] = a.w;
            float4 b = *(const float4*)(lw + (size_t)(kt*64 + row) * CC + lc4);
            *(float4*)&Bs[row][lc4] = b;
        }
        __syncthreads();
        if (kt < 8) {
            #pragma unroll
            for (int rep = 0; rep < 4; rep++) {
                int row = lr + rep * 16;
                pa[rep] = *(const float4*)(g_U + (size_t)(eBase + row) * CSH
                                           + (kt+1)*64 + lc4);
            }
        }
        #pragma unroll 8
        for (int k = 0; k < 64; k++) {
            float4 a4 = *(const float4*)&As[k*64 + ((ty ^ (k >> 2)) << 2)];
            ulonglong2 bv = *(const ulonglong2*)&Bs[k][tx*4];
            unsigned long long a0 = pk2(a4.x), a1 = pk2(a4.y);
            unsigned long long a2 = pk2(a4.z), a3 = pk2(a4.w);
            fma2(acc[0][0], a0, bv.x); fma2(acc[0][1], a0, bv.y);
            fma2(acc[1][0], a1, bv.x); fma2(acc[1][1], a1, bv.y);
            fma2(acc[2][0], a2, bv.x); fma2(acc[2][1], a2, bv.y);
            fma2(acc[3][0], a3, bv.x); fma2(acc[3][1], a3, bv.y);
        }
        __syncthreads();
    }
    #pragma unroll
    for (int i = 0; i < 4; i++) {
        int e = eBase + ty*4 + i;
        float mm = msk ? msk[e] : 1.f;
        if (mm != 0.f) {
            int s = src[e];
            float av[4];
            upk2(acc[i][0], av[0], av[1]);
            upk2(acc[i][1], av[2], av[3]);
            float* ap = agg + (size_t)s * CC + tx*4;
            atomicAdd(ap+0, av[0]);
            atomicAdd(ap+1, av[1]);
            atomicAdd(ap+2, av[2]);
            atomicAdd(ap+3, av[3]);
        }
    }
}

/* ------------------------- h_local + score MLP --------------------------- */
__global__ void k_update(const float* __restrict__ h)
{
    int t = blockIdx.x * blockDim.x + threadIdx.x;
    if (t >= NN * CC) return;
    int n = t >> 6;
    g_hloc[t] = g_agg[t] / fmaxf(g_deg[n], 1.f) + h[t];
}

__global__ __launch_bounds__(128)
void k_score(const float* __restrict__ w1, const float* __restrict__ b1,
             const float* __restrict__ w2, const float* __restrict__ b2)
{
    __shared__ float sw1[SD * 64];
    __shared__ float sb1[64];
    __shared__ float sw2[64];
    int tid = threadIdx.x;
    for (int t = tid; t < SD*64; t += 128) sw1[t] = w1[t];
    if (tid < 64) { sb1[tid] = b1[tid]; sw2[tid] = w2[tid]; }
    __syncthreads();
    int i = blockIdx.x * 128 + tid;
    if (i >= NN) return;
    float hs[SD];
    #pragma unroll
    for (int c = 0; c < SD; c++) hs[c] = g_hloc[(size_t)i * CC + c];
    float sum = 0.f;
    for (int j = 0; j < 64; j++) {
        float a = sb1[j];
        #pragma unroll
        for (int c = 0; c < SD; c++) a = fmaf(hs[c], sw1[c*64 + j], a);
        sum = fmaf(fmaxf(a, 0.f), sw2[j], sum);
    }
    g_score[i] = sigm(sum + b2[0]);
}

/* -------- exact top-K of scores (desc value, asc index tie-break) -------- */
__global__ __launch_bounds__(1024)
void k_topk()
{
    __shared__ unsigned hist[256];
    __shared__ unsigned ws[32];
    __shared__ unsigned sPre, sNeed;
    int tid = threadIdx.x;
    unsigned prefix = 0, need = KM;
    for (int round = 0; round < 4; round++) {
        int shift = 24 - 8*round;
        if (tid < 256) hist[tid] = 0;
        __syncthreads();
        for (int i = tid; i < NN; i += 1024) {
            unsigned f = fl(g_score[i]);
            if (round == 0 || (f >> (shift+8)) == (prefix >> (shift+8)))
                atomicAdd(&hist[(f >> shift) & 255], 1u);
        }
        __syncthreads();
        if (tid == 0) {
            unsigned cum = 0; int b = 255;
            for (; b > 0; b--) { unsigned c = hist[b]; if (cum + c >= need) break; cum += c; }
            sPre = prefix | ((unsigned)b << shift);
            sNeed = need - cum;
        }
        __syncthreads();
        prefix = sPre; need = sNeed;
        __syncthreads();
    }
    unsigned T = prefix, needTie = need;
    unsigned runSel = 0, runTie = 0;
    for (int base = 0; base < NN; base += 1024) {
        int i = base + tid;
        int valid = i < NN;
        float sc = valid ? g_score[i] : 0.f;
        unsigned f = valid ? fl(sc) : 0u;
        unsigned isGt  = (valid && f >  T) ? 1u : 0u;
        unsigned isTie = (valid && f == T) ? 1u : 0u;
        unsigned pk = isGt | (isTie << 16);
        unsigned incl = blockScanIncl(pk, ws);
        unsigned excl = incl - pk;
        unsigned gtE = excl & 0xFFFFu, tieE = excl >> 16;
        unsigned remTie = (needTie > runTie) ? needTie - runTie : 0u;
        int take = isGt || (isTie && tieE < remTie);
        unsigned rank = runSel + gtE + (tieE < remTie ? tieE : remTie);
        if (valid) {
            if (take) { g_master[rank] = i; g_node2m[i] = (int)rank; g_m[i] = sc; }
            else      { g_node2m[i] = -1;   g_m[i] = 0.f; }
        }
        unsigned tot = ws[31];
        unsigned totGt = tot & 0xFFFFu, totTie = tot >> 16;
        runSel += totGt + (totTie < remTie ? totTie : remTie);
        runTie += totTie;
        __syncthreads();
    }
}

/* ----------------------- master gather + q/k ----------------------------- */
__global__ void k_master(const float* __restrict__ pos)
{
    int t = blockIdx.x * blockDim.x + threadIdx.x;
    if (t < KM * CC) {
        int j = t >> 6, c = t & 63;
        g_hm[t] = g_hloc[(size_t)g_master[j] * CC + c];
    }
    if (t < KM * 3) {
        g_posm[t] = pos[(size_t)g_master[t/3] * 3 + (t - (t/3)*3)];
    }
}

__global__ void k_qk(const float* __restrict__ wq, const float* __restrict__ wk)
{
    int t = blockIdx.x * blockDim.x + threadIdx.x;
    if (t >= KM * 32) return;
    int j = t >> 5, u = t & 31;
    const float* hm = g_hm + (size_t)j * CC;
    if (u < 16) {
        float a = 0.f;
        #pragma unroll
        for (int i = 0; i < SD; i++) a = fmaf(hm[i], wq[i*SD + u], a);
        g_q[j*SD + u] = a;
    } else {
        int uu = u - 16;
        float a = 0.f;
        #pragma unroll
        for (int i = 0; i < SD; i++) a = fmaf(hm[i], wk[i*SD + uu], a);
        g_kk[j*SD + uu] = a;
    }
}

/* ----------------- adjacency scatter + master edge remap ----------------- */
__global__ void k_adjsc(const int* __restrict__ src, const int* __restrict__ dst)
{
    int e = blockIdx.x * blockDim.x + threadIdx.x;
    if (e >= EE) return;
    int sm = g_node2m[src[e]], dm = g_node2m[dst[e]];
    int ok = (sm >= 0) && (dm >= 0);
    g_src2[e] = sm >= 0 ? sm : 0;
    g_dst2[e] = dm >= 0 ? dm : 0;
    g_mask2[e] = ok ? 1.f : 0.f;
    if (ok) atomicAdd(&g_adj[(size_t)sm * KM + dm], 1.f);
}

/* ------------------- attention + A_virtual + candidates ------------------ */
__global__ __launch_bounds__(1024)
void k_attn(float* __restrict__ outA)
{
    __shared__ float qt[32][16];
    __shared__ float kt[32][17];
    int j0 = blockIdx.x * 32, i0 = blockIdx.y * 32;
    int tx = threadIdx.x, ty = threadIdx.y;
    int i = i0 + ty, j = j0 + tx;
    if (tx < 16) {
        qt[ty][tx] = (i < KM) ? g_q[(size_t)i*SD + tx] : 0.f;
        kt[ty][tx] = (j0 + ty < KM) ? g_kk[(size_t)(j0+ty)*SD + tx] : 0.f;
    }
    __syncthreads();
    int p = 0;
    if (i < KM && j < KM) {
        float d = 0.f;
        #pragma unroll
        for (int t = 0; t < SD; t++) d = fmaf(qt[ty][t], kt[tx][t], d);
        float at = sigm(d * 0.25f);
        bool exist = (g_adj[(size_t)i*KM + j] > 0.f) || (i == j);
        float av = (!exist && at > 0.5f) ? 1.f : 0.f;
        outA[(size_t)i*KM + j] = av;
        float cd = av * at;
        g_cand[(size_t)i*KM + j] = cd;
        p = cd > 0.f;
    }
    int cnt = __syncthreads_count(p);
    if (tx == 0 && ty == 0 && cnt) atomicAdd(&g_state[5], (unsigned)cnt);
}

/* ----------------- global radix select for top-E_V edges ----------------- */
__global__ __launch_bounds__(256)
void k_ghist(int shift, int first)
{
    __shared__ unsigned h[256];
    if (threadIdx.x < 256) h[threadIdx.x] = 0;
    __syncthreads();
    unsigned prefix = g_state[0];
    int n = KM * KM;
    for (int i = blockIdx.x * blockDim.x + threadIdx.x; i < n;
         i += gridDim.x * blockDim.x) {
        unsigned f = fl(g_cand[i]);
        if (first || (f >> (shift+8)) == (prefix >> (shift+8)))
            atomicAdd(&h[(f >> shift) & 255], 1u);
    }
    __syncthreads();
    if (threadIdx.x < 256 && h[threadIdx.x])
        atomicAdd(&g_hist[threadIdx.x], h[threadIdx.x]);
}

__global__ void k_gpick(int shift, int last)
{
    __shared__ unsigned h[256];
    int tid = threadIdx.x;
    h[tid] = g_hist[tid];
    __syncthreads();
    if (tid == 0) {
        unsigned need = g_state[3], prefix = g_state[0];
        unsigned cum = 0; int b = 255;
        for (; b > 0; b--) { unsigned c = h[b]; if (cum + c >= need) break; cum += c; }
        g_state[0] = prefix | ((unsigned)b << shift);
        g_state[3] = need - cum;
        if (last) {
            unsigned T = g_state[0];
            if (T <= FLIP_ZERO) {
                g_state[1] = FLIP_ZERO; g_state[2] = 0;
                g_state[7] = g_state[5]; g_state[4] = g_state[5];
            } else {
                g_state[1] = T; g_state[2] = g_state[3];
                g_state[7] = EV; g_state[4] = EV - g_state[3];
            }
            g_state[6] = 0;
        }
    }
    g_hist[tid] = 0;
}

__global__ void k_emit_gt()
{
    int i = blockIdx.x * blockDim.x + threadIdx.x;
    if (i >= KM * KM) return;
    unsigned f = fl(g_cand[i]);
    if (f > g_state[1]) {
        unsigned s = atomicAdd(&g_state[6], 1u);
        g_src2[EE + s] = i / KM;
        g_dst2[EE + s] = i - (i / KM) * KM;
        g_mask2[EE + s] = 1.f;
    }
}

__global__ __launch_bounds__(1024)
void k_tiecount()
{
    unsigned T = g_state[1], needT = g_state[2];
    int i = blockIdx.x * 1024 + threadIdx.x;
    int p = (needT > 0) && (i < KM*KM) && (fl(g_cand[i]) == T);
    int c = __syncthreads_count(p);
    if (threadIdx.x == 0) g_tiecnt[blockIdx.x] = (unsigned)c;
}

__global__ __launch_bounds__(1024)
void k_tiescan()
{
    __shared__ unsigned ws[32];
    unsigned run = 0;
    for (int base = 0; base < NBT; base += 1024) {
        int i = base + (int)threadIdx.x;
        unsigned v = (i < NBT) ? g_tiecnt[i] : 0u;
        unsigned incl = blockScanIncl(v, ws);
        if (i < NBT) g_tieoff[i] = run + incl - v;
        unsigned tot = ws[31];
        run += tot;
        __syncthreads();
    }
}

__global__ __launch_bounds__(1024)
void k_emit_tie()
{
    __shared__ unsigned ws[32];
    unsigned T = g_state[1], needT = g_state[2];
    int i = blockIdx.x * 1024 + threadIdx.x;
    unsigned p = (needT > 0) && (i < KM*KM) && (fl(g_cand[i]) == T);
    unsigned incl = blockScanIncl(p, ws);
    unsigned rank = g_tieoff[blockIdx.x] + incl - p;
    if (p && rank < needT) {
        unsigned s = g_state[4] + rank;
        g_src2[EE + s] = i / KM;
        g_dst2[EE + s] = i - (i / KM) * KM;
        g_mask2[EE + s] = 1.f;
    }
}

__global__ void k_fill_dummy()
{
    int t = blockIdx.x * blockDim.x + threadIdx.x;
    if (t >= EV) return;
    if ((unsigned)t >= g_state[7]) {
        g_src2[EE + t] = 0; g_dst2[EE + t] = 0; g_mask2[EE + t] = 0.f;
    }
}

/* ------------------------------ epilogue --------------------------------- */
__global__ void k_hier()
{
    int t = blockIdx.x * blockDim.x + threadIdx.x;
    if (t >= KM * CC) return;
    g_hhier[t] = g_agg2[t] / fmaxf(g_deg2[t >> 6], 1.f) + g_hm[t];
}

__global__ void k_final(float* __restrict__ out)
{
    int t = blockIdx.x * blockDim.x + threadIdx.x;
    if (t >= NN * CC) return;
    int n = t >> 6;
    float mm = g_m[n];
    int j = g_node2m[n];
    float hh = (j >= 0) ? g_hhier[(size_t)j * CC + (t & 63)] : 0.f;
    out[OUT_H + t] = (1.f - mm) * g_hloc[t] + mm * hh;
}

__global__ void k_aux(const float* __restrict__ pos, float* __restrict__ out)
{
    int t = blockIdx.x * blockDim.x + threadIdx.x;
    if (t < NN * 3) out[OUT_POS + t] = pos[t];
    if (t < NN)     out[OUT_M + t]   = g_m[t];
}

/* ------------------------------- launch ---------------------------------- */
extern "C" void kernel_launch(void* const* d_in, const int* in_sizes, int n_in,
                              void* d_out, int out_size)
{
    const float *h=0,*pos=0,*fw1=0,*fb1=0,*fw2=0,*fb2=0,*linw=0;
    const float *mw1=0,*mb1=0,*mw2=0,*mb2=0,*vq=0,*vk=0;
    const int *ei=0;
    int n64 = 0, n36 = 0, n256 = 0;
    for (int i = 0; i < n_in; i++) {
        int s = in_sizes[i]; const void* p = d_in[i];
        if      (s == NN*CC)   h   = (const float*)p;
        else if (s == NN*3)    pos = (const float*)p;
        else if (s == 2*EE)    ei  = (const int*)p;
        else if (s == 8*CC)    fw1 = (const float*)p;
        else if (s == CC*CSH) { if (n36 == 0) fw2 = (const float*)p; else linw = (const float*)p; n36++; }
        else if (s == CSH)     fb2 = (const float*)p;
        else if (s == CC)    { if (n64 == 0) fb1 = (const float*)p;
                               else if (n64 == 1) mb1 = (const float*)p;
                               else mw2 = (const float*)p; n64++; }
        else if (s == SD*64)   mw1 = (const float*)p;
        else if (s == 1)       mb2 = (const float*)p;
        else if (s == SD*SD) { if (n256 == 0) vq = (const float*)p; else vk = (const float*)p; n256++; }
    }
    const int* src = ei;
    const int* dst = ei + EE;
    float* out = (float*)d_out;

    k_clear<<<4096, 256>>>();

    /* conv 1 on the full graph */
    k_geom <<<(EE+255)/256, 256>>>(0, src, dst, pos, fw1, fb1, EE);
    k_gemm1<<<EE/64, 256>>>(0, h, dst, fw2, fb2);
    k_gemm2<<<EE/64, 256>>>(0, src, linw);
    k_update<<<(NN*CC+255)/256, 256>>>(h);
    k_score <<<(NN+127)/128, 128>>>(mw1, mb1, mw2, mb2);

    /* master selection + attention graph */
    k_topk  <<<1, 1024>>>();
    k_master<<<(KM*CC+255)/256, 256>>>(pos);
    k_qk    <<<(KM*32+255)/256, 256>>>(vq, vk);
    k_adjsc <<<(EE+255)/256, 256>>>(src, dst);
    k_attn  <<<dim3((KM+31)/32, (KM+31)/32), dim3(32,32)>>>(out + OUT_A);

    /* exact top-EV over 4M candidates */
    k_ghist<<<1024, 256>>>(24, 1); k_gpick<<<1, 256>>>(24, 0);
    k_ghist<<<1024, 256>>>(16, 0); k_gpick<<<1, 256>>>(16, 0);
    k_ghist<<<1024, 256>>>( 8, 0); k_gpick<<<1, 256>>>( 8, 0);
    k_ghist<<<1024, 256>>>( 0, 0); k_gpick<<<1, 256>>>( 0, 1);
    k_emit_gt  <<<(KM*KM+255)/256, 256>>>();
    k_tiecount <<<NBT, 1024>>>();
    k_tiescan  <<<1, 1024>>>();
    k_emit_tie <<<NBT, 1024>>>();
    k_fill_dummy<<<(EV+255)/256, 256>>>();

    /* conv 2 on the master graph (real + virtual edges) */
    k_geom <<<(E2+255)/256, 256>>>(1, 0, 0, 0, fw1, fb1, E2);
    k_gemm1<<<E2/64, 256>>>(1, 0, 0, fw2, fb2);
    k_gemm2<<<E2/64, 256>>>(1, 0, linw);
    k_hier <<<(KM*CC+255)/256, 256>>>();

    /* outputs */
    k_final<<<(NN*CC+255)/256, 256>>>(out);
    k_aux  <<<(NN*3+255)/256, 256>>>(pos, out);
    (void)out_size; (void)n_in;
}